// round 12
// baseline (speedup 1.0000x reference)
#include <cuda_runtime.h>
#include <cuda_fp16.h>
#include <math.h>
#include <stdint.h>

#define NN 100000
#define NE 1600000
#define SCAN_NBLK 98                  // ceil(NN/1024)
#define GEMM_BLKS ((NN + 127) / 128)  // 782

// ---------------- scratch (static device globals; no allocation) ----------------
__device__ __align__(16) __half g_h1h[(size_t)NN * 128]; // layer-1 features fp16
__device__ __align__(16) __half g_w2h[(size_t)NN * 40];  // layer-2 features fp16
__device__ float g_ai1[NN * 8];
__device__ float g_aj1[NN * 8];
__device__ float g_ai2[NN];
__device__ float g_aj2[NN];
__device__ int   g_deg[NN];           // zero-init at load; scan1 re-zeros each pass
__device__ int   g_rowptr[NN + 1];
__device__ int   g_cur[NN];
__device__ int   g_csr[NE];
__device__ int   g_bsums[SCAN_NBLK];

// ---------------- f32x2 packed-FMA helpers (SASS FFMA2) ----------------
__device__ __forceinline__ void ffma2(unsigned long long& acc,
                                      unsigned long long a, unsigned long long b) {
    asm("fma.rn.f32x2 %0, %1, %2, %0;" : "+l"(acc) : "l"(a), "l"(b));
}
__device__ __forceinline__ unsigned long long pack2(float x, float y) {
    unsigned long long v;
    asm("mov.b64 %0, {%1, %2};" : "=l"(v)
        : "r"(__float_as_uint(x)), "r"(__float_as_uint(y)));
    return v;
}
__device__ __forceinline__ float2 unpack2(unsigned long long v) {
    unsigned lo, hi;
    asm("mov.b64 {%0, %1}, %2;" : "=r"(lo), "=r"(hi) : "l"(v));
    return make_float2(__uint_as_float(lo), __uint_as_float(hi));
}

// ---------------- CSR build ----------------
__global__ void k_hist(const int* __restrict__ dst) {
    int i = blockIdx.x * blockDim.x + threadIdx.x;
    if (i < NE / 4) {
        int4 d = ((const int4*)dst)[i];
        atomicAdd(&g_deg[d.x], 1);
        atomicAdd(&g_deg[d.y], 1);
        atomicAdd(&g_deg[d.z], 1);
        atomicAdd(&g_deg[d.w], 1);
    }
}

__global__ void k_scan1() {
    __shared__ int sh[1024];
    int i = blockIdx.x * 1024 + threadIdx.x;
    int v = (i < NN) ? g_deg[i] : 0;
    if (i < NN) g_deg[i] = 0;          // re-zero for next graph replay
    sh[threadIdx.x] = v;
    __syncthreads();
    for (int off = 1; off < 1024; off <<= 1) {
        int t = (threadIdx.x >= off) ? sh[threadIdx.x - off] : 0;
        __syncthreads();
        sh[threadIdx.x] += t;
        __syncthreads();
    }
    if (i < NN) g_rowptr[i] = sh[threadIdx.x] - v;   // exclusive within block
    if (threadIdx.x == 1023) g_bsums[blockIdx.x] = sh[1023];
}

__global__ void k_scan3() {
    __shared__ int wsum[32];
    __shared__ int pre_s;
    const int tid = threadIdx.x;

    int acc = (tid < SCAN_NBLK && tid < blockIdx.x) ? g_bsums[tid] : 0;
    #pragma unroll
    for (int off = 16; off; off >>= 1)
        acc += __shfl_xor_sync(0xffffffffu, acc, off);
    if ((tid & 31) == 0) wsum[tid >> 5] = acc;
    __syncthreads();
    if (tid == 0) {
        int s = 0;
        #pragma unroll
        for (int w = 0; w < 4; ++w) s += wsum[w];
        pre_s = s;
    }
    __syncthreads();

    int i = blockIdx.x * 1024 + tid;
    if (i < NN) {
        int v = g_rowptr[i] + pre_s;
        g_rowptr[i] = v;
        g_cur[i] = v;
    }
    if (blockIdx.x == SCAN_NBLK - 1 && tid == 0)
        g_rowptr[NN] = pre_s + g_bsums[SCAN_NBLK - 1];   // == NE
}

__global__ void k_scatter(const int* __restrict__ src, const int* __restrict__ dst) {
    int i = blockIdx.x * blockDim.x + threadIdx.x;
    if (i < NE / 4) {
        int4 s = ((const int4*)src)[i];
        int4 d = ((const int4*)dst)[i];
        int p0 = atomicAdd(&g_cur[d.x], 1); g_csr[p0] = s.x;
        int p1 = atomicAdd(&g_cur[d.y], 1); g_csr[p1] = s.y;
        int p2 = atomicAdd(&g_cur[d.z], 1); g_csr[p2] = s.z;
        int p3 = atomicAdd(&g_cur[d.w], 1); g_csr[p3] = s.w;
    }
}

// ---------------- GEMM1: h1 = x @ W1^T + b1 (fp16 out) ; fused a_i1/a_j1 ----------------
__global__ void __launch_bounds__(256, 2)
k_gemm1(const float* __restrict__ x, const float* __restrict__ W1,
        const float* __restrict__ b1, const float* __restrict__ att1) {
    extern __shared__ float sm[];
    float* As = sm;                 // [64][132]  As[k][row]
    float* Ws = sm + 64 * 132;      // [64][132]  Ws[k][col]
    const int tid = threadIdx.x;
    const int tx = tid & 15;        // col group (8 cols)
    const int ty = tid >> 4;        // row group (8 rows)
    const int r0 = blockIdx.x * 128;

    unsigned long long acc[4][8];   // row-pairs x cols
    #pragma unroll
    for (int rp = 0; rp < 4; ++rp)
        #pragma unroll
        for (int c = 0; c < 8; ++c) acc[rp][c] = 0ull;

    const int lr = tid >> 1;               // 0..127
    const int khalf = (tid & 1) * 32;      // k offset within 64-chunk

    for (int kc = 0; kc < 128; kc += 64) {
        __syncthreads();
        {
            int gr = min(r0 + lr, NN - 1);
            const float4* xr = (const float4*)(x + (size_t)gr * 128 + kc + khalf);
            #pragma unroll
            for (int i = 0; i < 8; ++i) {
                float4 v = xr[i];
                int k = khalf + i * 4;
                As[(k + 0) * 132 + lr] = v.x;
                As[(k + 1) * 132 + lr] = v.y;
                As[(k + 2) * 132 + lr] = v.z;
                As[(k + 3) * 132 + lr] = v.w;
            }
        }
        {
            const float4* wr = (const float4*)(W1 + (size_t)lr * 128 + kc + khalf);
            #pragma unroll
            for (int i = 0; i < 8; ++i) {
                float4 v = wr[i];
                int k = khalf + i * 4;
                Ws[(k + 0) * 132 + lr] = v.x;
                Ws[(k + 1) * 132 + lr] = v.y;
                Ws[(k + 2) * 132 + lr] = v.z;
                Ws[(k + 3) * 132 + lr] = v.w;
            }
        }
        __syncthreads();

        #pragma unroll 2
        for (int k = 0; k < 64; ++k) {
            const float* as = As + k * 132 + ty * 8;
            ulonglong2 A0 = *(const ulonglong2*)as;
            ulonglong2 A1 = *(const ulonglong2*)(as + 4);
            float4 w0 = *(const float4*)(Ws + k * 132 + tx * 8);
            float4 w1 = *(const float4*)(Ws + k * 132 + tx * 8 + 4);
            unsigned long long ap[4] = {A0.x, A0.y, A1.x, A1.y};
            unsigned long long wp[8];
            wp[0] = pack2(w0.x, w0.x); wp[1] = pack2(w0.y, w0.y);
            wp[2] = pack2(w0.z, w0.z); wp[3] = pack2(w0.w, w0.w);
            wp[4] = pack2(w1.x, w1.x); wp[5] = pack2(w1.y, w1.y);
            wp[6] = pack2(w1.z, w1.z); wp[7] = pack2(w1.w, w1.w);
            #pragma unroll
            for (int rp = 0; rp < 4; ++rp)
                #pragma unroll
                for (int c = 0; c < 8; ++c)
                    ffma2(acc[rp][c], ap[rp], wp[c]);
        }
    }

    // epilogue
    float bo[8], ati[8], atj[8];
    const int head = tx >> 1, c0 = (tx & 1) * 8;
    #pragma unroll
    for (int j = 0; j < 8; ++j) {
        bo[j]  = b1[tx * 8 + j];
        ati[j] = att1[head * 32 + c0 + j];
        atj[j] = att1[head * 32 + 16 + c0 + j];
    }
    #pragma unroll
    for (int rp = 0; rp < 4; ++rp) {
        #pragma unroll
        for (int half = 0; half < 2; ++half) {
            int r = r0 + ty * 8 + rp * 2 + half;
            float v[8];
            #pragma unroll
            for (int c = 0; c < 8; ++c) {
                float2 f = unpack2(acc[rp][c]);
                v[c] = (half ? f.y : f.x) + bo[c];
            }
            float pi = 0.f, pj = 0.f;
            #pragma unroll
            for (int c = 0; c < 8; ++c) {
                pi = fmaf(v[c], ati[c], pi);
                pj = fmaf(v[c], atj[c], pj);
            }
            pi += __shfl_xor_sync(0xffffffffu, pi, 1);
            pj += __shfl_xor_sync(0xffffffffu, pj, 1);
            if (r < NN) {
                __half2 h0 = __floats2half2_rn(v[0], v[1]);
                __half2 h1 = __floats2half2_rn(v[2], v[3]);
                __half2 h2 = __floats2half2_rn(v[4], v[5]);
                __half2 h3 = __floats2half2_rn(v[6], v[7]);
                uint4 pk;
                pk.x = *(unsigned*)&h0; pk.y = *(unsigned*)&h1;
                pk.z = *(unsigned*)&h2; pk.w = *(unsigned*)&h3;
                *(uint4*)(g_h1h + (size_t)r * 128 + tx * 8) = pk;
                if ((tx & 1) == 0) {
                    g_ai1[r * 8 + head] = pi;
                    g_aj1[r * 8 + head] = pj;
                }
            }
        }
    }
}

// ---------------- edge accumulate for layer-1 aggregation ----------------
__device__ __forceinline__ void edge1_acc(int s, float ai, int lane, int head,
                                          float4& acc, float& den) {
    float aj = __ldg(&g_aj1[s * 8 + head]);
    float e = ai + aj;
    e = fmaxf(e, 0.2f * e);
    float ex = __expf(e);
    uint2 rv = *(const uint2*)(g_h1h + (size_t)s * 128 + lane * 4);
    float2 f0 = __half22float2(*(const __half2*)&rv.x);
    float2 f1 = __half22float2(*(const __half2*)&rv.y);
    acc.x = fmaf(ex, f0.x, acc.x);
    acc.y = fmaf(ex, f0.y, acc.y);
    acc.z = fmaf(ex, f1.x, acc.z);
    acc.w = fmaf(ex, f1.y, acc.w);
    den += ex;
}

// ---------------- FUSED: agg1 (+bias1+ELU) -> smem z ; gemm2 + a_i2/a_j2 ----------------
// block = 128 nodes. Phase A: 8 warps x 16 nodes each, z rows -> Zs[row][132] (f32).
// Phase B: w2 = z @ W2^T + b2 from smem; fp16 store + attention scalars.
__global__ void __launch_bounds__(256, 2)
k_agg1gemm2(const float* __restrict__ bias1, const float* __restrict__ W2,
            const float* __restrict__ b2, const float* __restrict__ att2) {
    extern __shared__ float sm[];
    float* Zs  = sm;               // [128][132] row-major (node, k)
    float* Ws2 = sm + 128 * 132;   // [40][132]  col-major (outc, k)
    const int tid  = threadIdx.x;
    const int lane = tid & 31;
    const int warp = tid >> 5;
    const int r0   = blockIdx.x * 128;

    // fill Ws2 (transposed-padded W2)
    for (int i = tid; i < 40 * 128; i += 256) {
        int o = i >> 7, k = i & 127;
        Ws2[o * 132 + k] = W2[(size_t)o * 128 + k];
    }

    // ---- Phase A: aggregation ----
    const int head = lane >> 2;
    float4 bb = *(const float4*)(bias1 + lane * 4);

    #pragma unroll 1
    for (int t = 0; t < 16; ++t) {
        const int lr = warp * 16 + t;
        const int n  = r0 + lr;
        float o0 = 0.f, o1 = 0.f, o2 = 0.f, o3 = 0.f;
        if (n < NN) {
            const float ai = __ldg(&g_ai1[n * 8 + head]);
            float4 acc = make_float4(0.f, 0.f, 0.f, 0.f);
            float den = 0.f;
            edge1_acc(n, ai, lane, head, acc, den);   // self loop
            int i = g_rowptr[n];
            const int end = g_rowptr[n + 1];
            for (; i + 8 <= end; i += 8) {
                int s0 = __ldg(&g_csr[i + 0]);
                int s1 = __ldg(&g_csr[i + 1]);
                int s2 = __ldg(&g_csr[i + 2]);
                int s3 = __ldg(&g_csr[i + 3]);
                int s4 = __ldg(&g_csr[i + 4]);
                int s5 = __ldg(&g_csr[i + 5]);
                int s6 = __ldg(&g_csr[i + 6]);
                int s7 = __ldg(&g_csr[i + 7]);
                edge1_acc(s0, ai, lane, head, acc, den);
                edge1_acc(s1, ai, lane, head, acc, den);
                edge1_acc(s2, ai, lane, head, acc, den);
                edge1_acc(s3, ai, lane, head, acc, den);
                edge1_acc(s4, ai, lane, head, acc, den);
                edge1_acc(s5, ai, lane, head, acc, den);
                edge1_acc(s6, ai, lane, head, acc, den);
                edge1_acc(s7, ai, lane, head, acc, den);
            }
            for (; i < end; ++i)
                edge1_acc(__ldg(&g_csr[i]), ai, lane, head, acc, den);

            float inv = 1.f / (den + 1e-16f);
            o0 = fmaf(acc.x, inv, bb.x);
            o1 = fmaf(acc.y, inv, bb.y);
            o2 = fmaf(acc.z, inv, bb.z);
            o3 = fmaf(acc.w, inv, bb.w);
            o0 = o0 > 0.f ? o0 : expm1f(o0);
            o1 = o1 > 0.f ? o1 : expm1f(o1);
            o2 = o2 > 0.f ? o2 : expm1f(o2);
            o3 = o3 > 0.f ? o3 : expm1f(o3);
        }
        *(float4*)(Zs + lr * 132 + lane * 4) = make_float4(o0, o1, o2, o3);
    }
    __syncthreads();

    // ---- Phase B: gemm2 from smem ----
    const int tx = tid & 7;          // 5 cols
    const int ty = tid >> 3;         // 4 rows
    float acc2[4][5];
    #pragma unroll
    for (int j = 0; j < 4; ++j)
        #pragma unroll
        for (int c = 0; c < 5; ++c) acc2[j][c] = 0.f;

    #pragma unroll 2
    for (int k0 = 0; k0 < 128; k0 += 4) {
        float4 a[4], w[5];
        #pragma unroll
        for (int j = 0; j < 4; ++j)
            a[j] = *(const float4*)(Zs + (ty * 4 + j) * 132 + k0);
        #pragma unroll
        for (int c = 0; c < 5; ++c)
            w[c] = *(const float4*)(Ws2 + (tx * 5 + c) * 132 + k0);
        #pragma unroll
        for (int j = 0; j < 4; ++j)
            #pragma unroll
            for (int c = 0; c < 5; ++c) {
                acc2[j][c] = fmaf(a[j].x, w[c].x, acc2[j][c]);
                acc2[j][c] = fmaf(a[j].y, w[c].y, acc2[j][c]);
                acc2[j][c] = fmaf(a[j].z, w[c].z, acc2[j][c]);
                acc2[j][c] = fmaf(a[j].w, w[c].w, acc2[j][c]);
            }
    }

    float bo[5], ati[5], atj[5];
    #pragma unroll
    for (int c = 0; c < 5; ++c) {
        bo[c]  = b2[tx * 5 + c];
        ati[c] = att2[tx * 5 + c];
        atj[c] = att2[40 + tx * 5 + c];
    }
    #pragma unroll
    for (int j = 0; j < 4; ++j) {
        int r = r0 + ty * 4 + j;
        float pi = 0.f, pj = 0.f;
        float v[5];
        #pragma unroll
        for (int c = 0; c < 5; ++c) {
            v[c] = acc2[j][c] + bo[c];
            pi = fmaf(v[c], ati[c], pi);
            pj = fmaf(v[c], atj[c], pj);
        }
        #pragma unroll
        for (int off = 1; off < 8; off <<= 1) {
            pi += __shfl_xor_sync(0xffffffffu, pi, off);
            pj += __shfl_xor_sync(0xffffffffu, pj, off);
        }
        if (r < NN) {
            #pragma unroll
            for (int c = 0; c < 5; ++c)
                g_w2h[(size_t)r * 40 + tx * 5 + c] = __float2half_rn(v[c]);
            if (tx == 0) { g_ai2[r] = pi; g_aj2[r] = pj; }
        }
    }
}

// ---------------- Aggregation layer 2 + bias2 + fused log_softmax ----------------
__device__ __forceinline__ void edge2_acc(int s, float ai, int lane, bool act,
                                          float2& acc, float& den) {
    float aj = __ldg(&g_aj2[s]);
    float e = ai + aj;
    e = fmaxf(e, 0.2f * e);
    float ex = __expf(e);
    if (act) {
        unsigned pk = *(const unsigned*)(g_w2h + (size_t)s * 40 + lane * 2);
        float2 f = __half22float2(*(const __half2*)&pk);
        acc.x = fmaf(ex, f.x, acc.x);
        acc.y = fmaf(ex, f.y, acc.y);
    }
    den += ex;
}

__global__ void k_agg2(const float* __restrict__ bias2, float* __restrict__ out) {
    int gw = (blockIdx.x * blockDim.x + threadIdx.x) >> 5;
    if (gw >= NN) return;
    const int lane = threadIdx.x & 31;
    const bool act = lane < 20;

    const float ai = __ldg(&g_ai2[gw]);
    float2 acc = make_float2(0.f, 0.f);
    float den = 0.f;

    edge2_acc(gw, ai, lane, act, acc, den);   // self loop

    int i = g_rowptr[gw];
    const int end = g_rowptr[gw + 1];
    for (; i + 8 <= end; i += 8) {
        int s0 = __ldg(&g_csr[i + 0]);
        int s1 = __ldg(&g_csr[i + 1]);
        int s2 = __ldg(&g_csr[i + 2]);
        int s3 = __ldg(&g_csr[i + 3]);
        int s4 = __ldg(&g_csr[i + 4]);
        int s5 = __ldg(&g_csr[i + 5]);
        int s6 = __ldg(&g_csr[i + 6]);
        int s7 = __ldg(&g_csr[i + 7]);
        edge2_acc(s0, ai, lane, act, acc, den);
        edge2_acc(s1, ai, lane, act, acc, den);
        edge2_acc(s2, ai, lane, act, acc, den);
        edge2_acc(s3, ai, lane, act, acc, den);
        edge2_acc(s4, ai, lane, act, acc, den);
        edge2_acc(s5, ai, lane, act, acc, den);
        edge2_acc(s6, ai, lane, act, acc, den);
        edge2_acc(s7, ai, lane, act, acc, den);
    }
    for (; i < end; ++i)
        edge2_acc(__ldg(&g_csr[i]), ai, lane, act, acc, den);

    float inv = 1.f / (den + 1e-16f);
    float o0 = -INFINITY, o1 = -INFINITY;
    if (act) {
        o0 = fmaf(acc.x, inv, bias2[lane * 2]);
        o1 = fmaf(acc.y, inv, bias2[lane * 2 + 1]);
    }

    float m = fmaxf(o0, o1);
    #pragma unroll
    for (int off = 16; off; off >>= 1)
        m = fmaxf(m, __shfl_xor_sync(0xffffffffu, m, off));
    float s = act ? (expf(o0 - m) + expf(o1 - m)) : 0.f;
    #pragma unroll
    for (int off = 16; off; off >>= 1)
        s += __shfl_xor_sync(0xffffffffu, s, off);
    float lse = m + logf(s);

    if (act) {
        out[(size_t)gw * 40 + lane * 2]     = o0 - lse;
        out[(size_t)gw * 40 + lane * 2 + 1] = o1 - lse;
    }
}

// ---------------- launch ----------------
extern "C" void kernel_launch(void* const* d_in, const int* in_sizes, int n_in,
                              void* d_out, int out_size) {
    const float* x     = (const float*)d_in[0];
    const int*   ei    = (const int*)d_in[1];
    const float* W1    = (const float*)d_in[2];
    const float* b1    = (const float*)d_in[3];
    const float* att1  = (const float*)d_in[4];
    const float* bias1 = (const float*)d_in[5];
    const float* W2    = (const float*)d_in[6];
    const float* b2    = (const float*)d_in[7];
    const float* att2  = (const float*)d_in[8];
    const float* bias2 = (const float*)d_in[9];
    float* out = (float*)d_out;

    const int* src = ei;
    const int* dst = ei + NE;

    const int smem1 = 2 * 64 * 132 * (int)sizeof(float);          // 67584 B
    const int smem_fused = (128 * 132 + 40 * 132) * (int)sizeof(float); // 88704 B

    // one-time resource setup (streams/events are resources, not work)
    static cudaStream_t s_csr = nullptr;
    static cudaEvent_t ev_fork = nullptr, ev_csr = nullptr;
    static bool s_init = false;
    if (!s_init) {
        cudaStreamCreateWithFlags(&s_csr, cudaStreamNonBlocking);
        cudaEventCreateWithFlags(&ev_fork, cudaEventDisableTiming);
        cudaEventCreateWithFlags(&ev_csr, cudaEventDisableTiming);
        cudaFuncSetAttribute(k_gemm1, cudaFuncAttributeMaxDynamicSharedMemorySize, smem1);
        cudaFuncSetAttribute(k_agg1gemm2, cudaFuncAttributeMaxDynamicSharedMemorySize, smem_fused);
        s_init = true;
    }

    // fork: CSR chain on side stream, gemm1 on main stream — independent
    cudaEventRecord(ev_fork, 0);
    cudaStreamWaitEvent(s_csr, ev_fork, 0);

    k_hist   <<<(NE / 4 + 255) / 256, 256, 0, s_csr>>>(dst);
    k_scan1  <<<SCAN_NBLK, 1024, 0, s_csr>>>();
    k_scan3  <<<SCAN_NBLK, 1024, 0, s_csr>>>();
    k_scatter<<<(NE / 4 + 255) / 256, 256, 0, s_csr>>>(src, dst);
    cudaEventRecord(ev_csr, s_csr);

    k_gemm1<<<GEMM_BLKS, 256, smem1>>>(x, W1, b1, att1);   // main stream, concurrent

    // join: everything after needs both branches
    cudaStreamWaitEvent(0, ev_csr, 0);

    k_agg1gemm2<<<GEMM_BLKS, 256, smem_fused>>>(bias1, W2, b2, att2);
    k_agg2<<<(NN * 32 + 255) / 256, 256>>>(bias2, out);
}

// round 13
// speedup vs baseline: 1.1675x; 1.1675x over previous
#include <cuda_runtime.h>
#include <cuda_fp16.h>
#include <math.h>
#include <stdint.h>

#define NN 100000
#define NE 1600000
#define SCAN_NBLK 98                  // ceil(NN/1024)
#define GEMM_BLKS ((NN + 127) / 128)  // 782

// ---------------- scratch (static device globals; no allocation) ----------------
__device__ __align__(16) __half g_h1h[(size_t)NN * 128]; // layer-1 features fp16
__device__ __align__(16) __half g_zh[(size_t)NN * 128];  // elu(agg1) output fp16
__device__ __align__(16) __half g_w2h[(size_t)NN * 40];  // layer-2 features fp16
__device__ float g_ai1[NN * 8];
__device__ float g_aj1[NN * 8];
__device__ float g_ai2[NN];
__device__ float g_aj2[NN];
__device__ int   g_deg[NN];           // zero-init at load; scan1 re-zeros each pass
__device__ int   g_rowptr[NN + 1];
__device__ int   g_cur[NN];
__device__ int   g_csr[NE];
__device__ int   g_bsums[SCAN_NBLK];

// ---------------- f32x2 packed-FMA helpers (SASS FFMA2) ----------------
__device__ __forceinline__ void ffma2(unsigned long long& acc,
                                      unsigned long long a, unsigned long long b) {
    asm("fma.rn.f32x2 %0, %1, %2, %0;" : "+l"(acc) : "l"(a), "l"(b));
}
__device__ __forceinline__ unsigned long long pack2(float x, float y) {
    unsigned long long v;
    asm("mov.b64 %0, {%1, %2};" : "=l"(v)
        : "r"(__float_as_uint(x)), "r"(__float_as_uint(y)));
    return v;
}
__device__ __forceinline__ float2 unpack2(unsigned long long v) {
    unsigned lo, hi;
    asm("mov.b64 {%0, %1}, %2;" : "=r"(lo), "=r"(hi) : "l"(v));
    return make_float2(__uint_as_float(lo), __uint_as_float(hi));
}

// ---------------- CSR build ----------------
__global__ void k_hist(const int* __restrict__ dst) {
    int i = blockIdx.x * blockDim.x + threadIdx.x;
    if (i < NE / 4) {
        int4 d = ((const int4*)dst)[i];
        atomicAdd(&g_deg[d.x], 1);
        atomicAdd(&g_deg[d.y], 1);
        atomicAdd(&g_deg[d.z], 1);
        atomicAdd(&g_deg[d.w], 1);
    }
}

__global__ void k_scan1() {
    __shared__ int sh[1024];
    int i = blockIdx.x * 1024 + threadIdx.x;
    int v = (i < NN) ? g_deg[i] : 0;
    if (i < NN) g_deg[i] = 0;          // re-zero for next graph replay
    sh[threadIdx.x] = v;
    __syncthreads();
    for (int off = 1; off < 1024; off <<= 1) {
        int t = (threadIdx.x >= off) ? sh[threadIdx.x - off] : 0;
        __syncthreads();
        sh[threadIdx.x] += t;
        __syncthreads();
    }
    if (i < NN) g_rowptr[i] = sh[threadIdx.x] - v;   // exclusive within block
    if (threadIdx.x == 1023) g_bsums[blockIdx.x] = sh[1023];
}

__global__ void k_scan3() {
    __shared__ int wsum[32];
    __shared__ int pre_s;
    const int tid = threadIdx.x;

    int acc = (tid < SCAN_NBLK && tid < blockIdx.x) ? g_bsums[tid] : 0;
    #pragma unroll
    for (int off = 16; off; off >>= 1)
        acc += __shfl_xor_sync(0xffffffffu, acc, off);
    if ((tid & 31) == 0) wsum[tid >> 5] = acc;
    __syncthreads();
    if (tid == 0) {
        int s = 0;
        #pragma unroll
        for (int w = 0; w < 4; ++w) s += wsum[w];
        pre_s = s;
    }
    __syncthreads();

    int i = blockIdx.x * 1024 + tid;
    if (i < NN) {
        int v = g_rowptr[i] + pre_s;
        g_rowptr[i] = v;
        g_cur[i] = v;
    }
    if (blockIdx.x == SCAN_NBLK - 1 && tid == 0)
        g_rowptr[NN] = pre_s + g_bsums[SCAN_NBLK - 1];   // == NE
}

__global__ void k_scatter(const int* __restrict__ src, const int* __restrict__ dst) {
    int i = blockIdx.x * blockDim.x + threadIdx.x;
    if (i < NE / 4) {
        int4 s = ((const int4*)src)[i];
        int4 d = ((const int4*)dst)[i];
        int p0 = atomicAdd(&g_cur[d.x], 1); g_csr[p0] = s.x;
        int p1 = atomicAdd(&g_cur[d.y], 1); g_csr[p1] = s.y;
        int p2 = atomicAdd(&g_cur[d.z], 1); g_csr[p2] = s.z;
        int p3 = atomicAdd(&g_cur[d.w], 1); g_csr[p3] = s.w;
    }
}

// ---------------- GEMM1: h1 = x @ W1^T + b1 (fp16 out) ; fused a_i1/a_j1 ----------------
// A tile fp32 [64][132]; W tile fp16 [64][136] (halves crossbar bytes on the
// non-broadcast operand). fp32 accumulate via FFMA2.
__global__ void __launch_bounds__(256, 2)
k_gemm1(const float* __restrict__ x, const float* __restrict__ W1,
        const float* __restrict__ b1, const float* __restrict__ att1) {
    extern __shared__ char smraw[];
    float*  As  = (float*)smraw;                    // [64][132]  As[k][row]
    __half* Wsh = (__half*)(smraw + 64 * 132 * 4);  // [64][136]  Wsh[k][col]
    const int tid = threadIdx.x;
    const int tx = tid & 15;        // col group (8 cols)
    const int ty = tid >> 4;        // row group (8 rows)
    const int r0 = blockIdx.x * 128;

    unsigned long long acc[4][8];   // row-pairs x cols
    #pragma unroll
    for (int rp = 0; rp < 4; ++rp)
        #pragma unroll
        for (int c = 0; c < 8; ++c) acc[rp][c] = 0ull;

    const int lr = tid >> 1;               // 0..127
    const int khalf = (tid & 1) * 32;      // k offset within 64-chunk

    for (int kc = 0; kc < 128; kc += 64) {
        __syncthreads();
        // fill As (transpose of x tile, fp32)
        {
            int gr = min(r0 + lr, NN - 1);
            const float4* xr = (const float4*)(x + (size_t)gr * 128 + kc + khalf);
            #pragma unroll
            for (int i = 0; i < 8; ++i) {
                float4 v = xr[i];
                int k = khalf + i * 4;
                As[(k + 0) * 132 + lr] = v.x;
                As[(k + 1) * 132 + lr] = v.y;
                As[(k + 2) * 132 + lr] = v.z;
                As[(k + 3) * 132 + lr] = v.w;
            }
        }
        // fill Wsh (transpose of W1, fp16)
        {
            const float4* wr = (const float4*)(W1 + (size_t)lr * 128 + kc + khalf);
            #pragma unroll
            for (int i = 0; i < 8; ++i) {
                float4 v = wr[i];
                int k = khalf + i * 4;
                Wsh[(k + 0) * 136 + lr] = __float2half_rn(v.x);
                Wsh[(k + 1) * 136 + lr] = __float2half_rn(v.y);
                Wsh[(k + 2) * 136 + lr] = __float2half_rn(v.z);
                Wsh[(k + 3) * 136 + lr] = __float2half_rn(v.w);
            }
        }
        __syncthreads();

        #pragma unroll 2
        for (int k = 0; k < 64; ++k) {
            const float* as = As + k * 132 + ty * 8;
            ulonglong2 A0 = *(const ulonglong2*)as;        // rows 0,1 | 2,3
            ulonglong2 A1 = *(const ulonglong2*)(as + 4);  // rows 4,5 | 6,7
            uint4 wv = *(const uint4*)(Wsh + k * 136 + tx * 8);  // 8 fp16 cols
            float2 f0 = __half22float2(*(const __half2*)&wv.x);  // c0,c1
            float2 f1 = __half22float2(*(const __half2*)&wv.y);  // c2,c3
            float2 f2 = __half22float2(*(const __half2*)&wv.z);  // c4,c5
            float2 f3 = __half22float2(*(const __half2*)&wv.w);  // c6,c7
            unsigned long long ap[4] = {A0.x, A0.y, A1.x, A1.y};
            unsigned long long wp[8];
            wp[0] = pack2(f0.x, f0.x); wp[1] = pack2(f0.y, f0.y);
            wp[2] = pack2(f1.x, f1.x); wp[3] = pack2(f1.y, f1.y);
            wp[4] = pack2(f2.x, f2.x); wp[5] = pack2(f2.y, f2.y);
            wp[6] = pack2(f3.x, f3.x); wp[7] = pack2(f3.y, f3.y);
            #pragma unroll
            for (int rp = 0; rp < 4; ++rp)
                #pragma unroll
                for (int c = 0; c < 8; ++c)
                    ffma2(acc[rp][c], ap[rp], wp[c]);
        }
    }

    // epilogue
    float bo[8], ati[8], atj[8];
    const int head = tx >> 1, c0 = (tx & 1) * 8;
    #pragma unroll
    for (int j = 0; j < 8; ++j) {
        bo[j]  = b1[tx * 8 + j];
        ati[j] = att1[head * 32 + c0 + j];
        atj[j] = att1[head * 32 + 16 + c0 + j];
    }
    #pragma unroll
    for (int rp = 0; rp < 4; ++rp) {
        #pragma unroll
        for (int half = 0; half < 2; ++half) {
            int r = r0 + ty * 8 + rp * 2 + half;
            float v[8];
            #pragma unroll
            for (int c = 0; c < 8; ++c) {
                float2 f = unpack2(acc[rp][c]);
                v[c] = (half ? f.y : f.x) + bo[c];
            }
            float pi = 0.f, pj = 0.f;
            #pragma unroll
            for (int c = 0; c < 8; ++c) {
                pi = fmaf(v[c], ati[c], pi);
                pj = fmaf(v[c], atj[c], pj);
            }
            pi += __shfl_xor_sync(0xffffffffu, pi, 1);
            pj += __shfl_xor_sync(0xffffffffu, pj, 1);
            if (r < NN) {
                __half2 h0 = __floats2half2_rn(v[0], v[1]);
                __half2 h1 = __floats2half2_rn(v[2], v[3]);
                __half2 h2 = __floats2half2_rn(v[4], v[5]);
                __half2 h3 = __floats2half2_rn(v[6], v[7]);
                uint4 pk;
                pk.x = *(unsigned*)&h0; pk.y = *(unsigned*)&h1;
                pk.z = *(unsigned*)&h2; pk.w = *(unsigned*)&h3;
                *(uint4*)(g_h1h + (size_t)r * 128 + tx * 8) = pk;
                if ((tx & 1) == 0) {
                    g_ai1[r * 8 + head] = pi;
                    g_aj1[r * 8 + head] = pj;
                }
            }
        }
    }
}

// ---------------- Aggregation layer 1 (+ bias1 + ELU) -> g_zh (fp16) ----------------
__device__ __forceinline__ void edge1_acc(int s, float ai, int lane, int head,
                                          float4& acc, float& den) {
    float aj = __ldg(&g_aj1[s * 8 + head]);
    float e = ai + aj;
    e = fmaxf(e, 0.2f * e);
    float ex = __expf(e);
    uint2 rv = *(const uint2*)(g_h1h + (size_t)s * 128 + lane * 4);
    float2 f0 = __half22float2(*(const __half2*)&rv.x);
    float2 f1 = __half22float2(*(const __half2*)&rv.y);
    acc.x = fmaf(ex, f0.x, acc.x);
    acc.y = fmaf(ex, f0.y, acc.y);
    acc.z = fmaf(ex, f1.x, acc.z);
    acc.w = fmaf(ex, f1.y, acc.w);
    den += ex;
}

__global__ void k_agg1(const float* __restrict__ bias1) {
    int gw = (blockIdx.x * blockDim.x + threadIdx.x) >> 5;
    if (gw >= NN) return;
    const int lane = threadIdx.x & 31;
    const int head = lane >> 2;

    const float ai = __ldg(&g_ai1[gw * 8 + head]);
    float4 acc = make_float4(0.f, 0.f, 0.f, 0.f);
    float den = 0.f;

    edge1_acc(gw, ai, lane, head, acc, den);   // self loop

    int i = g_rowptr[gw];
    const int end = g_rowptr[gw + 1];
    for (; i + 8 <= end; i += 8) {
        int s0 = __ldg(&g_csr[i + 0]);
        int s1 = __ldg(&g_csr[i + 1]);
        int s2 = __ldg(&g_csr[i + 2]);
        int s3 = __ldg(&g_csr[i + 3]);
        int s4 = __ldg(&g_csr[i + 4]);
        int s5 = __ldg(&g_csr[i + 5]);
        int s6 = __ldg(&g_csr[i + 6]);
        int s7 = __ldg(&g_csr[i + 7]);
        edge1_acc(s0, ai, lane, head, acc, den);
        edge1_acc(s1, ai, lane, head, acc, den);
        edge1_acc(s2, ai, lane, head, acc, den);
        edge1_acc(s3, ai, lane, head, acc, den);
        edge1_acc(s4, ai, lane, head, acc, den);
        edge1_acc(s5, ai, lane, head, acc, den);
        edge1_acc(s6, ai, lane, head, acc, den);
        edge1_acc(s7, ai, lane, head, acc, den);
    }
    for (; i < end; ++i)
        edge1_acc(__ldg(&g_csr[i]), ai, lane, head, acc, den);

    float inv = 1.f / (den + 1e-16f);
    float4 bb = *(const float4*)(bias1 + lane * 4);
    float o0 = fmaf(acc.x, inv, bb.x);
    float o1 = fmaf(acc.y, inv, bb.y);
    float o2 = fmaf(acc.z, inv, bb.z);
    float o3 = fmaf(acc.w, inv, bb.w);
    o0 = o0 > 0.f ? o0 : expm1f(o0);
    o1 = o1 > 0.f ? o1 : expm1f(o1);
    o2 = o2 > 0.f ? o2 : expm1f(o2);
    o3 = o3 > 0.f ? o3 : expm1f(o3);
    __half2 z0 = __floats2half2_rn(o0, o1);
    __half2 z1 = __floats2half2_rn(o2, o3);
    uint2 pk;
    pk.x = *(unsigned*)&z0; pk.y = *(unsigned*)&z1;
    *(uint2*)(g_zh + (size_t)gw * 128 + lane * 4) = pk;
}

// ---------------- GEMM2: w2 = zh @ W2^T + b2 (fp16 out) ; fused a_i2/a_j2 ----------------
__global__ void __launch_bounds__(256, 2)
k_gemm2(const float* __restrict__ W2, const float* __restrict__ b2,
        const float* __restrict__ att2) {
    __shared__ float Zs[64 * 132];   // Zs[k][row]
    __shared__ float Ws[64 * 40];    // Ws[k][col]
    const int tid = threadIdx.x;
    const int tx = tid & 7;          // 5 cols
    const int ty = tid >> 3;         // 4 rows
    const int r0 = blockIdx.x * 128;

    float acc[4][5];
    #pragma unroll
    for (int j = 0; j < 4; ++j)
        #pragma unroll
        for (int c = 0; c < 5; ++c) acc[j][c] = 0.f;

    const int lr = tid >> 1;
    const int khalf = (tid & 1) * 32;

    for (int kc = 0; kc < 128; kc += 64) {
        __syncthreads();
        {
            int gr = min(r0 + lr, NN - 1);
            const uint4* zr = (const uint4*)(g_zh + (size_t)gr * 128 + kc + khalf);
            #pragma unroll
            for (int i = 0; i < 4; ++i) {        // 4 x uint4 = 32 halves
                uint4 v = zr[i];
                int k = khalf + i * 8;
                float2 f0 = __half22float2(*(const __half2*)&v.x);
                float2 f1 = __half22float2(*(const __half2*)&v.y);
                float2 f2 = __half22float2(*(const __half2*)&v.z);
                float2 f3 = __half22float2(*(const __half2*)&v.w);
                Zs[(k + 0) * 132 + lr] = f0.x;
                Zs[(k + 1) * 132 + lr] = f0.y;
                Zs[(k + 2) * 132 + lr] = f1.x;
                Zs[(k + 3) * 132 + lr] = f1.y;
                Zs[(k + 4) * 132 + lr] = f2.x;
                Zs[(k + 5) * 132 + lr] = f2.y;
                Zs[(k + 6) * 132 + lr] = f3.x;
                Zs[(k + 7) * 132 + lr] = f3.y;
            }
        }
        for (int i = tid; i < 40 * 64; i += 256) {
            int o = i >> 6, k = i & 63;
            Ws[k * 40 + o] = W2[(size_t)o * 128 + kc + k];
        }
        __syncthreads();

        #pragma unroll 2
        for (int k = 0; k < 64; ++k) {
            float4 a = *(const float4*)(Zs + k * 132 + ty * 4);
            const float* wrow = Ws + k * 40 + tx * 5;
            #pragma unroll
            for (int c = 0; c < 5; ++c) {
                float w = wrow[c];
                acc[0][c] = fmaf(a.x, w, acc[0][c]);
                acc[1][c] = fmaf(a.y, w, acc[1][c]);
                acc[2][c] = fmaf(a.z, w, acc[2][c]);
                acc[3][c] = fmaf(a.w, w, acc[3][c]);
            }
        }
    }

    float bo[5], ati[5], atj[5];
    #pragma unroll
    for (int c = 0; c < 5; ++c) {
        bo[c]  = b2[tx * 5 + c];
        ati[c] = att2[tx * 5 + c];
        atj[c] = att2[40 + tx * 5 + c];
    }
    #pragma unroll
    for (int j = 0; j < 4; ++j) {
        int r = r0 + ty * 4 + j;
        float pi = 0.f, pj = 0.f;
        float v[5];
        #pragma unroll
        for (int c = 0; c < 5; ++c) {
            v[c] = acc[j][c] + bo[c];
            pi = fmaf(v[c], ati[c], pi);
            pj = fmaf(v[c], atj[c], pj);
        }
        #pragma unroll
        for (int off = 1; off < 8; off <<= 1) {
            pi += __shfl_xor_sync(0xffffffffu, pi, off);
            pj += __shfl_xor_sync(0xffffffffu, pj, off);
        }
        if (r < NN) {
            #pragma unroll
            for (int c = 0; c < 5; ++c)
                g_w2h[(size_t)r * 40 + tx * 5 + c] = __float2half_rn(v[c]);
            if (tx == 0) { g_ai2[r] = pi; g_aj2[r] = pj; }
        }
    }
}

// ---------------- Aggregation layer 2 + bias2 + fused log_softmax ----------------
__device__ __forceinline__ void edge2_acc(int s, float ai, int lane, bool act,
                                          float2& acc, float& den) {
    float aj = __ldg(&g_aj2[s]);
    float e = ai + aj;
    e = fmaxf(e, 0.2f * e);
    float ex = __expf(e);
    if (act) {
        unsigned pk = *(const unsigned*)(g_w2h + (size_t)s * 40 + lane * 2);
        float2 f = __half22float2(*(const __half2*)&pk);
        acc.x = fmaf(ex, f.x, acc.x);
        acc.y = fmaf(ex, f.y, acc.y);
    }
    den += ex;
}

__global__ void k_agg2(const float* __restrict__ bias2, float* __restrict__ out) {
    int gw = (blockIdx.x * blockDim.x + threadIdx.x) >> 5;
    if (gw >= NN) return;
    const int lane = threadIdx.x & 31;
    const bool act = lane < 20;

    const float ai = __ldg(&g_ai2[gw]);
    float2 acc = make_float2(0.f, 0.f);
    float den = 0.f;

    edge2_acc(gw, ai, lane, act, acc, den);   // self loop

    int i = g_rowptr[gw];
    const int end = g_rowptr[gw + 1];
    for (; i + 8 <= end; i += 8) {
        int s0 = __ldg(&g_csr[i + 0]);
        int s1 = __ldg(&g_csr[i + 1]);
        int s2 = __ldg(&g_csr[i + 2]);
        int s3 = __ldg(&g_csr[i + 3]);
        int s4 = __ldg(&g_csr[i + 4]);
        int s5 = __ldg(&g_csr[i + 5]);
        int s6 = __ldg(&g_csr[i + 6]);
        int s7 = __ldg(&g_csr[i + 7]);
        edge2_acc(s0, ai, lane, act, acc, den);
        edge2_acc(s1, ai, lane, act, acc, den);
        edge2_acc(s2, ai, lane, act, acc, den);
        edge2_acc(s3, ai, lane, act, acc, den);
        edge2_acc(s4, ai, lane, act, acc, den);
        edge2_acc(s5, ai, lane, act, acc, den);
        edge2_acc(s6, ai, lane, act, acc, den);
        edge2_acc(s7, ai, lane, act, acc, den);
    }
    for (; i < end; ++i)
        edge2_acc(__ldg(&g_csr[i]), ai, lane, act, acc, den);

    float inv = 1.f / (den + 1e-16f);
    float o0 = -INFINITY, o1 = -INFINITY;
    if (act) {
        o0 = fmaf(acc.x, inv, bias2[lane * 2]);
        o1 = fmaf(acc.y, inv, bias2[lane * 2 + 1]);
    }

    float m = fmaxf(o0, o1);
    #pragma unroll
    for (int off = 16; off; off >>= 1)
        m = fmaxf(m, __shfl_xor_sync(0xffffffffu, m, off));
    float s = act ? (expf(o0 - m) + expf(o1 - m)) : 0.f;
    #pragma unroll
    for (int off = 16; off; off >>= 1)
        s += __shfl_xor_sync(0xffffffffu, s, off);
    float lse = m + logf(s);

    if (act) {
        out[(size_t)gw * 40 + lane * 2]     = o0 - lse;
        out[(size_t)gw * 40 + lane * 2 + 1] = o1 - lse;
    }
}

// ---------------- launch ----------------
extern "C" void kernel_launch(void* const* d_in, const int* in_sizes, int n_in,
                              void* d_out, int out_size) {
    const float* x     = (const float*)d_in[0];
    const int*   ei    = (const int*)d_in[1];
    const float* W1    = (const float*)d_in[2];
    const float* b1    = (const float*)d_in[3];
    const float* att1  = (const float*)d_in[4];
    const float* bias1 = (const float*)d_in[5];
    const float* W2    = (const float*)d_in[6];
    const float* b2    = (const float*)d_in[7];
    const float* att2  = (const float*)d_in[8];
    const float* bias2 = (const float*)d_in[9];
    float* out = (float*)d_out;

    const int* src = ei;
    const int* dst = ei + NE;

    const int smem1 = 64 * 132 * 4 + 64 * 136 * 2;   // 33792 + 17408 = 51200 B

    // one-time resource setup (streams/events are resources, not work; every
    // call issues the identical launch DAG)
    static cudaStream_t s_csr = nullptr;
    static cudaEvent_t ev_fork = nullptr, ev_csr = nullptr;
    static bool s_init = false;
    if (!s_init) {
        cudaStreamCreateWithFlags(&s_csr, cudaStreamNonBlocking);
        cudaEventCreateWithFlags(&ev_fork, cudaEventDisableTiming);
        cudaEventCreateWithFlags(&ev_csr, cudaEventDisableTiming);
        cudaFuncSetAttribute(k_gemm1, cudaFuncAttributeMaxDynamicSharedMemorySize, smem1);
        s_init = true;
    }

    // fork: CSR chain on side stream, gemm1 on main stream — independent
    cudaEventRecord(ev_fork, 0);
    cudaStreamWaitEvent(s_csr, ev_fork, 0);

    k_hist   <<<(NE / 4 + 255) / 256, 256, 0, s_csr>>>(dst);
    k_scan1  <<<SCAN_NBLK, 1024, 0, s_csr>>>();
    k_scan3  <<<SCAN_NBLK, 1024, 0, s_csr>>>();
    k_scatter<<<(NE / 4 + 255) / 256, 256, 0, s_csr>>>(src, dst);
    cudaEventRecord(ev_csr, s_csr);

    k_gemm1<<<GEMM_BLKS, 256, smem1>>>(x, W1, b1, att1);   // main stream, concurrent

    // join: everything after needs both branches
    cudaStreamWaitEvent(0, ev_csr, 0);

    k_agg1 <<<(NN * 32 + 255) / 256, 256>>>(bias1);
    k_gemm2<<<GEMM_BLKS, 256>>>(W2, b2, att2);
    k_agg2 <<<(NN * 32 + 255) / 256, 256>>>(bias2, out);
}